// round 2
// baseline (speedup 1.0000x reference)
#include <cuda_runtime.h>
#include <math.h>

// Model dims
// B=64, T=512, F=161, V=32, L=64, H=128, E=32
// conv1: (64,1,512,161) -> (64,32,241,80), w (32,1,32,2), stride 2
// conv2: (64,32,241,80) -> (64,32,105,36), w (32,32,32,9), stride 2
// reshape -> (64,105,1152); enc GRU H=128, 105 steps
// decoder: 63 steps, attention over 105 enc states, fc -> (64,63,32)

#define NB 64
#define C1H 241
#define C1W 80
#define C2H 105
#define C2W 36

// ---------------- device scratch (no allocations allowed) ----------------
__device__ float g_conv1[NB * 32 * C1H * C1W];   // 39,485,440
__device__ float g_conv2[NB * C2H * 1152];       // 7,741,440  (b, t, c*36+w)
__device__ float g_xp   [NB * C2H * 384];
__device__ float g_eh   [NB * C2H * 128];
__device__ float g_embA [NB * 63 * 32];
__device__ float g_ip   [NB * 63 * 384];
__device__ float g_ctxs [NB * 63 * 128];
__device__ float g_wT   [128 * 384];             // dec_w_hh transposed (k-major)

// ---------------- conv1: normalize + conv + relu ----------------
// grid (241, 64), 256 threads. Block = one (b, oh): all 32 c_out x 80 ow.
__global__ void conv1_kernel(const float* __restrict__ x,
                             const float* __restrict__ mean,
                             const float* __restrict__ stdv,
                             const float* __restrict__ w,
                             const float* __restrict__ bias) {
    int oh = blockIdx.x, b = blockIdx.y;
    __shared__ float s_x[32 * 161];
    __shared__ float s_w[2048];
    int tid = threadIdx.x;
    for (int i = tid; i < 32 * 161; i += 256) {
        int kh = i / 161, iw = i % 161;
        int ih = 2 * oh + kh;
        s_x[i] = (x[(b * 512 + ih) * 161 + iw] - mean[iw]) / stdv[iw];
    }
    for (int i = tid; i < 2048; i += 256) s_w[i] = w[i];
    __syncthreads();

    int c = tid >> 3, owb = tid & 7;
    float acc[10];
#pragma unroll
    for (int j = 0; j < 10; j++) acc[j] = 0.f;
    for (int kh = 0; kh < 32; kh++) {
        float w0 = s_w[c * 64 + kh * 2], w1 = s_w[c * 64 + kh * 2 + 1];
        const float* xr = &s_x[kh * 161];
#pragma unroll
        for (int j = 0; j < 10; j++) {
            int ow = owb + 8 * j;
            acc[j] += w0 * xr[2 * ow] + w1 * xr[2 * ow + 1];
        }
    }
    float bb = bias[c];
#pragma unroll
    for (int j = 0; j < 10; j++) {
        int ow = owb + 8 * j;
        float v = acc[j] + bb;
        g_conv1[((size_t)(b * 32 + c) * C1H + oh) * C1W + ow] = v > 0.f ? v : 0.f;
    }
}

// ---------------- conv2 + relu + reshape to (b,t,1152) ----------------
// grid (105, 64), 192 threads. Block = one (b, oh): 32 c_out x 36 ow.
// Thread = one c_out, 6 consecutive ow. Loop kh: stage input row + weight slice in smem.
__global__ void conv2_kernel(const float* __restrict__ w,
                             const float* __restrict__ bias) {
    int oh = blockIdx.x, b = blockIdx.y;
    __shared__ __align__(16) float s_in[2560];   // 32 ci x 80 iw
    __shared__ float s_w[9216];                  // [co][ci][kw]
    int tid = threadIdx.x;                       // 192
    int c_out = tid / 6;
    int ow0 = (tid % 6) * 6;
    float acc[6] = {0.f, 0.f, 0.f, 0.f, 0.f, 0.f};

    for (int kh = 0; kh < 32; kh++) {
        int ih = 2 * oh + kh;
        for (int i = tid; i < 2560; i += 192) {
            int ci = i / 80, iw = i % 80;
            s_in[i] = g_conv1[((size_t)(b * 32 + ci) * C1H + ih) * C1W + iw];
        }
        for (int i = tid; i < 9216; i += 192) {
            int coci = i / 9, kw = i % 9;
            s_w[i] = w[coci * 288 + kh * 9 + kw];
        }
        __syncthreads();
#pragma unroll 4
        for (int ci = 0; ci < 32; ci++) {
            float rw[9];
            const float* wp = &s_w[(c_out * 32 + ci) * 9];
#pragma unroll
            for (int kw = 0; kw < 9; kw++) rw[kw] = wp[kw];
            const float4* xin = (const float4*)&s_in[ci * 80 + 2 * ow0];
            float xv[20];
#pragma unroll
            for (int q = 0; q < 5; q++) {
                float4 t4 = xin[q];
                xv[4 * q] = t4.x; xv[4 * q + 1] = t4.y;
                xv[4 * q + 2] = t4.z; xv[4 * q + 3] = t4.w;
            }
#pragma unroll
            for (int j = 0; j < 6; j++) {
#pragma unroll
                for (int kw = 0; kw < 9; kw++)
                    acc[j] += rw[kw] * xv[2 * j + kw];
            }
        }
        __syncthreads();
    }
    float bb = bias[c_out];
#pragma unroll
    for (int j = 0; j < 6; j++) {
        float v = acc[j] + bb;
        g_conv2[((size_t)b * C2H + oh) * 1152 + c_out * 36 + ow0 + j] = v > 0.f ? v : 0.f;
    }
}

// ---------------- generic C[M,N] = A[M,K] * B[N,K]^T + bias ----------------
// 128x128 tile, BK=8, 256 threads, 8x8 per thread.
__global__ void gemm_nt(const float* __restrict__ A, const float* __restrict__ Bm,
                        const float* __restrict__ bias, float* __restrict__ C,
                        int M, int N, int K) {
    __shared__ float sA[8][128];
    __shared__ float sB[8][128];
    int bm = blockIdx.y * 128, bn = blockIdx.x * 128;
    int tid = threadIdx.x;
    int ty = tid >> 4, tx = tid & 15;
    float acc[8][8];
#pragma unroll
    for (int i = 0; i < 8; i++)
#pragma unroll
        for (int j = 0; j < 8; j++) acc[i][j] = 0.f;

    int lrow = tid >> 1, lk = (tid & 1) * 4;
    for (int k0 = 0; k0 < K; k0 += 8) {
        float4 av = make_float4(0.f, 0.f, 0.f, 0.f);
        float4 bv = make_float4(0.f, 0.f, 0.f, 0.f);
        if (bm + lrow < M) av = *(const float4*)&A[(size_t)(bm + lrow) * K + k0 + lk];
        if (bn + lrow < N) bv = *(const float4*)&Bm[(size_t)(bn + lrow) * K + k0 + lk];
        sA[lk + 0][lrow] = av.x; sA[lk + 1][lrow] = av.y;
        sA[lk + 2][lrow] = av.z; sA[lk + 3][lrow] = av.w;
        sB[lk + 0][lrow] = bv.x; sB[lk + 1][lrow] = bv.y;
        sB[lk + 2][lrow] = bv.z; sB[lk + 3][lrow] = bv.w;
        __syncthreads();
#pragma unroll
        for (int k = 0; k < 8; k++) {
            float a[8], bb[8];
            *(float4*)&a[0] = *(const float4*)&sA[k][ty * 8];
            *(float4*)&a[4] = *(const float4*)&sA[k][ty * 8 + 4];
            *(float4*)&bb[0] = *(const float4*)&sB[k][tx * 8];
            *(float4*)&bb[4] = *(const float4*)&sB[k][tx * 8 + 4];
#pragma unroll
            for (int i = 0; i < 8; i++)
#pragma unroll
                for (int j = 0; j < 8; j++) acc[i][j] += a[i] * bb[j];
        }
        __syncthreads();
    }
    for (int i = 0; i < 8; i++) {
        int m = bm + ty * 8 + i;
        if (m >= M) break;
        for (int j = 0; j < 8; j++) {
            int n = bn + tx * 8 + j;
            if (n < N) C[(size_t)m * N + n] = acc[i][j] + bias[n];
        }
    }
}

// ---------------- encoder GRU: one block per batch element ----------------
// 384 threads; w_hh (384x128) resident in smem.
__global__ void encoder_kernel(const float* __restrict__ w_hh,
                               const float* __restrict__ b_hh) {
    extern __shared__ float sm[];
    float* s_w = sm;             // 49152
    float* s_h = sm + 49152;     // 128
    float* s_gh = sm + 49280;    // 384
    int b = blockIdx.x, tid = threadIdx.x;
    for (int i = tid; i < 49152; i += 384) s_w[i] = w_hh[i];
    if (tid < 128) s_h[tid] = 0.f;
    __syncthreads();
    float bn = b_hh[tid];
    const float4* wr = (const float4*)&s_w[tid * 128];
    for (int t = 0; t < 105; t++) {
        float acc = bn;
#pragma unroll 8
        for (int k = 0; k < 32; k++) {
            float4 wv = wr[k];
            float4 hv = ((const float4*)s_h)[k];
            acc += wv.x * hv.x + wv.y * hv.y + wv.z * hv.z + wv.w * hv.w;
        }
        s_gh[tid] = acc;
        __syncthreads();
        if (tid < 128) {
            const float* xrow = &g_xp[((size_t)b * 105 + t) * 384];
            float r = 1.f / (1.f + __expf(-(xrow[tid] + s_gh[tid])));
            float z = 1.f / (1.f + __expf(-(xrow[128 + tid] + s_gh[128 + tid])));
            float nn = tanhf(xrow[256 + tid] + r * s_gh[256 + tid]);
            float hnew = (1.f - z) * nn + z * s_h[tid];
            s_h[tid] = hnew;
            g_eh[((size_t)b * 105 + t) * 128 + tid] = hnew;
        }
        __syncthreads();
    }
}

// ---------------- decoder: GRU step + attention, one block per batch ----------------
__device__ __forceinline__ float warpred_max(float v) {
#pragma unroll
    for (int o = 16; o; o >>= 1) v = fmaxf(v, __shfl_xor_sync(0xffffffffu, v, o));
    return v;
}
__device__ __forceinline__ float warpred_sum(float v) {
#pragma unroll
    for (int o = 16; o; o >>= 1) v += __shfl_xor_sync(0xffffffffu, v, o);
    return v;
}

__global__ void decoder_kernel(const float* __restrict__ b_hh) {
    extern __shared__ float sm[];
    float* s_eh = sm;              // 105*132 = 13860 (padded stride vs bank conflicts)
    float* s_h = sm + 13860;       // 128 (carry = ctx)
    float* s_gh = sm + 13988;      // 384
    float* s_hx2 = sm + 14372;     // 128
    float* s_att = sm + 14500;     // 128
    float* s_red = sm + 14628;     // 32
    int b = blockIdx.x, tid = threadIdx.x;

    for (int i = tid; i < 13440; i += 384) {
        int t = i >> 7, k = i & 127;
        s_eh[t * 132 + k] = g_eh[(size_t)b * 105 * 128 + i];
    }
    if (tid < 128) s_h[tid] = 0.f;
    __syncthreads();

    float bn = b_hh[tid];
    for (int l = 0; l < 63; l++) {
        // gh = hx @ w_hh^T + b (w read k-major from global, coalesced, L2-resident)
        float acc = bn;
#pragma unroll 4
        for (int k = 0; k < 128; k++) acc += g_wT[k * 384 + tid] * s_h[k];
        s_gh[tid] = acc;
        __syncthreads();

        if (tid < 128) {
            const float* irow = &g_ip[((size_t)b * 63 + l) * 384];
            float r = 1.f / (1.f + __expf(-(irow[tid] + s_gh[tid])));
            float z = 1.f / (1.f + __expf(-(irow[128 + tid] + s_gh[128 + tid])));
            float nn = tanhf(irow[256 + tid] + r * s_gh[256 + tid]);
            s_hx2[tid] = (1.f - z) * nn + z * s_h[tid];
        }
        __syncthreads();

        // attention scores over 105 encoder states
        float sc = -1e30f;
        if (tid < 105) {
            const float4* er = (const float4*)&s_eh[tid * 132];
            const float4* hx = (const float4*)s_hx2;
            float d = 0.f;
#pragma unroll 8
            for (int k = 0; k < 32; k++) {
                float4 e4 = er[k], h4 = hx[k];
                d += e4.x * h4.x + e4.y * h4.y + e4.z * h4.z + e4.w * h4.w;
            }
            sc = d;
        }
        // block max
        float m = warpred_max(sc);
        if ((tid & 31) == 0) s_red[tid >> 5] = m;
        __syncthreads();
        if (tid < 32) {
            float wv = (tid < 12) ? s_red[tid] : -1e30f;
            wv = warpred_max(wv);
            if (tid == 0) s_red[12] = wv;
        }
        __syncthreads();
        float mx = s_red[12];
        float e = (tid < 105) ? __expf(sc - mx) : 0.f;
        float sv = warpred_sum(e);
        if ((tid & 31) == 0) s_red[16 + (tid >> 5)] = sv;
        if (tid < 128) s_att[tid] = e;
        __syncthreads();
        if (tid < 32) {
            float wv = (tid < 12) ? s_red[16 + tid] : 0.f;
            wv = warpred_sum(wv);
            if (tid == 0) s_red[13] = wv;
        }
        __syncthreads();
        float inv = 1.f / s_red[13];

        // ctx = softmax(s) @ eh  -> becomes next carry
        if (tid < 128) {
            float c = 0.f;
            for (int t = 0; t < 105; t++) c += s_att[t] * s_eh[t * 132 + tid];
            c *= inv;
            s_h[tid] = c;
            g_ctxs[((size_t)b * 63 + l) * 128 + tid] = c;
        }
        __syncthreads();
    }
}

// ---------------- small helpers ----------------
__global__ void emb_gather(const int* __restrict__ y, const float* __restrict__ emb) {
    int i = blockIdx.x * 256 + threadIdx.x;
    if (i >= NB * 63 * 32) return;
    int m = i >> 5, e = i & 31;
    int bb = m / 63, l = m % 63;
    int idx = y[bb * 64 + l];
    g_embA[i] = emb[idx * 32 + e];
}

__global__ void transpose_whh(const float* __restrict__ w) {
    int i = blockIdx.x * 256 + threadIdx.x;
    if (i < 49152) {
        int n = i >> 7, k = i & 127;
        g_wT[k * 384 + n] = w[i];
    }
}

// ---------------- launch ----------------
extern "C" void kernel_launch(void* const* d_in, const int* in_sizes, int n_in,
                              void* d_out, int out_size) {
    const float* x    = (const float*)d_in[0];
    const int*   y    = (const int*)d_in[1];
    const float* mean = (const float*)d_in[2];
    const float* stdv = (const float*)d_in[3];
    const float* c1w  = (const float*)d_in[4];
    const float* c1b  = (const float*)d_in[5];
    const float* c2w  = (const float*)d_in[6];
    const float* c2b  = (const float*)d_in[7];
    const float* gwih = (const float*)d_in[8];
    const float* gwhh = (const float*)d_in[9];
    const float* gbih = (const float*)d_in[10];
    const float* gbhh = (const float*)d_in[11];
    const float* emb  = (const float*)d_in[12];
    const float* dwih = (const float*)d_in[13];
    const float* dwhh = (const float*)d_in[14];
    const float* dbih = (const float*)d_in[15];
    const float* dbhh = (const float*)d_in[16];
    const float* fcw  = (const float*)d_in[17];
    const float* fcb  = (const float*)d_in[18];
    float* out = (float*)d_out;

    cudaFuncSetAttribute(encoder_kernel, cudaFuncAttributeMaxDynamicSharedMemorySize, 198656);
    cudaFuncSetAttribute(decoder_kernel, cudaFuncAttributeMaxDynamicSharedMemorySize, 58640);

    void *p_conv2, *p_xp, *p_embA, *p_ip, *p_ctxs;
    cudaGetSymbolAddress(&p_conv2, g_conv2);
    cudaGetSymbolAddress(&p_xp, g_xp);
    cudaGetSymbolAddress(&p_embA, g_embA);
    cudaGetSymbolAddress(&p_ip, g_ip);
    cudaGetSymbolAddress(&p_ctxs, g_ctxs);

    conv1_kernel<<<dim3(C1H, NB), 256>>>(x, mean, stdv, c1w, c1b);
    conv2_kernel<<<dim3(C2H, NB), 192>>>(c2w, c2b);
    // xp = conv_out @ gru_w_ih^T + gru_b_ih : (6720,1152)x(384,1152)
    gemm_nt<<<dim3(3, 53), 256>>>((const float*)p_conv2, gwih, gbih, (float*)p_xp,
                                  NB * C2H, 384, 1152);
    encoder_kernel<<<NB, 384, 198656>>>(gwhh, gbhh);

    emb_gather<<<(NB * 63 * 32 + 255) / 256, 256>>>(y, emb);
    // ip = emb_in @ dec_w_ih^T + dec_b_ih : (4032,32)x(384,32)
    gemm_nt<<<dim3(3, 32), 256>>>((const float*)p_embA, dwih, dbih, (float*)p_ip,
                                  NB * 63, 384, 32);
    transpose_whh<<<192, 256>>>(dwhh);
    decoder_kernel<<<NB, 384, 58640>>>(dbhh);
    // out = ctxs @ fc_w^T + fc_b : (4032,128)x(32,128)
    gemm_nt<<<dim3(1, 32), 256>>>((const float*)p_ctxs, fcw, fcb, out,
                                  NB * 63, 32, 128);
}

// round 3
// speedup vs baseline: 1.5419x; 1.5419x over previous
#include <cuda_runtime.h>
#include <math.h>

// Model dims
// B=64, T=512, F=161, V=32, L=64, H=128, E=32
// conv1: (64,1,512,161) -> (64,32,241,80), w (32,1,32,2), stride 2
// conv2: (64,32,241,80) -> (64,32,105,36), w (32,32,32,9), stride 2
// reshape -> (64,105,1152); enc GRU H=128, 105 steps
// decoder: 63 steps, attention over 105 enc states, fc -> (64,63,32)

#define NB 64
#define C1H 241
#define C1W 80
#define C2H 105
#define C2W 36

typedef unsigned long long ull;

// ---------------- device scratch (no allocations allowed) ----------------
__device__ float g_conv1[NB * 32 * C1H * C1W];   // 39,485,440
__device__ float g_conv2[NB * C2H * 1152];       // (b, t, c*36+w)
__device__ float g_xp   [NB * C2H * 384];
__device__ float g_eh   [NB * C2H * 128];
__device__ float g_embA [NB * 63 * 32];
__device__ float g_ip   [NB * 63 * 384];
__device__ float g_ctxs [NB * 63 * 128];
__device__ float g_wT   [128 * 384];             // dec_w_hh transposed (k-major)
__device__ float g_w2   [32 * 32 * 9 * 32];      // conv2 w as [kh][ci][kw][co]

// ---------------- f32x2 packed helpers (Blackwell FFMA2 path) ----------------
__device__ __forceinline__ ull pk2(float lo, float hi) {
    ull r;
    asm("mov.b64 %0, {%1, %2};" : "=l"(r) : "f"(lo), "f"(hi));
    return r;
}
__device__ __forceinline__ void fma2(ull& d, ull a, ull b) {
    asm("fma.rn.f32x2 %0, %1, %2, %0;" : "+l"(d) : "l"(a), "l"(b));
}
__device__ __forceinline__ void upk2(ull v, float& lo, float& hi) {
    asm("mov.b64 {%0, %1}, %2;" : "=f"(lo), "=f"(hi) : "l"(v));
}

// ---------------- conv1: normalize + conv + relu ----------------
__global__ void conv1_kernel(const float* __restrict__ x,
                             const float* __restrict__ mean,
                             const float* __restrict__ stdv,
                             const float* __restrict__ w,
                             const float* __restrict__ bias) {
    int oh = blockIdx.x, b = blockIdx.y;
    __shared__ float s_x[32 * 161];
    __shared__ float s_w[2048];
    int tid = threadIdx.x;
    for (int i = tid; i < 32 * 161; i += 256) {
        int kh = i / 161, iw = i % 161;
        int ih = 2 * oh + kh;
        s_x[i] = (x[(b * 512 + ih) * 161 + iw] - mean[iw]) / stdv[iw];
    }
    for (int i = tid; i < 2048; i += 256) s_w[i] = w[i];
    __syncthreads();

    int c = tid >> 3, owb = tid & 7;
    float acc[10];
#pragma unroll
    for (int j = 0; j < 10; j++) acc[j] = 0.f;
    for (int kh = 0; kh < 32; kh++) {
        float w0 = s_w[c * 64 + kh * 2], w1 = s_w[c * 64 + kh * 2 + 1];
        const float* xr = &s_x[kh * 161];
#pragma unroll
        for (int j = 0; j < 10; j++) {
            int ow = owb + 8 * j;
            acc[j] += w0 * xr[2 * ow] + w1 * xr[2 * ow + 1];
        }
    }
    float bb = bias[c];
#pragma unroll
    for (int j = 0; j < 10; j++) {
        int ow = owb + 8 * j;
        float v = acc[j] + bb;
        g_conv1[((size_t)(b * 32 + c) * C1H + oh) * C1W + ow] = v > 0.f ? v : 0.f;
    }
}

// ---------------- weight reorder for conv2: [co][ci][kh][kw] -> [kh][ci][kw][co] --
__global__ void reorder_w2(const float* __restrict__ w) {
    int i = blockIdx.x * 256 + threadIdx.x;
    if (i < 294912) {
        int kw = i % 9; int t = i / 9;
        int kh = t & 31; t >>= 5;
        int ci = t & 31; int co = t >> 5;
        g_w2[((kh * 32 + ci) * 9 + kw) * 32 + co] = w[i];
    }
}

// ---------------- conv2 + relu + reshape, packed f32x2 math ----------------
// grid (53, 64), 384 threads, dyn smem. Block = (b, oh0..oh0+1).
// Half-block (192 thr) per oh: c_out = ltid&31 (lane-consecutive -> conflict-free
// weight LDS), ow group g = ltid>>5 (warp-uniform -> broadcast x LDS).
// kw paired (0,1)(2,3)(4,5)(6,7): x pairs are contiguous & 8B-aligned in smem.
__global__ void conv2_kernel(const float* __restrict__ bias) {
    extern __shared__ __align__(16) float sm2[];
    float* s_in = sm2;            // 2 x 2560
    float* s_w  = sm2 + 5120;     // 9216 : [ci][kw][co]
    int oh0 = blockIdx.x * 2, b = blockIdx.y;
    int tid = threadIdx.x;        // 384
    int sub = (tid >= 192) ? 1 : 0;
    int ltid = tid - sub * 192;
    int c_out = ltid & 31;
    int g = ltid >> 5;            // 0..5 -> ow = 6g..6g+5
    int oh = oh0 + sub;
    bool valid = (oh < C2H);

    ull  acc2[6];
    float accs[6];
#pragma unroll
    for (int j = 0; j < 6; j++) { acc2[j] = 0ULL; accs[j] = 0.f; }

    for (int kh = 0; kh < 32; kh++) {
        int ih0 = 2 * oh0 + kh;
        for (int i = tid; i < 5120; i += 384) {
            int r = i / 2560, j = i % 2560;
            int ci = j / 80, iw = j % 80;
            int row = ih0 + 2 * r;
            s_in[i] = (row < C1H)
                ? g_conv1[((size_t)(b * 32 + ci) * C1H + row) * C1W + iw] : 0.f;
        }
        {
            const float4* src = (const float4*)&g_w2[kh * 9216];
            float4* dst = (float4*)s_w;
            for (int i = tid; i < 2304; i += 384) dst[i] = src[i];
        }
        __syncthreads();

#pragma unroll 2
        for (int ci = 0; ci < 32; ci++) {
            const float* xr = &s_in[sub * 2560 + ci * 80 + 12 * g];
            const ull*  x64 = (const ull*)xr;        // (ci*80 + 12g) is even
            ull xb[10];
#pragma unroll
            for (int q = 0; q < 10; q++) xb[q] = x64[q];
            float xs[6];
#pragma unroll
            for (int j = 0; j < 6; j++) xs[j] = xr[2 * j + 8];

            const float* wp = &s_w[ci * 288 + c_out];
            float w0 = wp[0],   w1 = wp[32],  w2 = wp[64],  w3 = wp[96];
            float w4 = wp[128], w5 = wp[160], w6 = wp[192], w7 = wp[224];
            float w8 = wp[256];
            ull wp01 = pk2(w0, w1), wp23 = pk2(w2, w3);
            ull wp45 = pk2(w4, w5), wp67 = pk2(w6, w7);
#pragma unroll
            for (int j = 0; j < 6; j++) {
                fma2(acc2[j], wp01, xb[j]);
                fma2(acc2[j], wp23, xb[j + 1]);
                fma2(acc2[j], wp45, xb[j + 2]);
                fma2(acc2[j], wp67, xb[j + 3]);
                accs[j] += w8 * xs[j];
            }
        }
        __syncthreads();
    }
    if (valid) {
        float bb = bias[c_out];
        float* dst = &g_conv2[((size_t)b * C2H + oh) * 1152 + c_out * 36 + 6 * g];
#pragma unroll
        for (int j = 0; j < 6; j++) {
            float lo, hi;
            upk2(acc2[j], lo, hi);
            float v = lo + hi + accs[j] + bb;
            dst[j] = v > 0.f ? v : 0.f;
        }
    }
}

// ---------------- generic C[M,N] = A[M,K] * B[N,K]^T + bias ----------------
__global__ void gemm_nt(const float* __restrict__ A, const float* __restrict__ Bm,
                        const float* __restrict__ bias, float* __restrict__ C,
                        int M, int N, int K) {
    __shared__ float sA[8][128];
    __shared__ float sB[8][128];
    int bm = blockIdx.y * 128, bn = blockIdx.x * 128;
    int tid = threadIdx.x;
    int ty = tid >> 4, tx = tid & 15;
    float acc[8][8];
#pragma unroll
    for (int i = 0; i < 8; i++)
#pragma unroll
        for (int j = 0; j < 8; j++) acc[i][j] = 0.f;

    int lrow = tid >> 1, lk = (tid & 1) * 4;
    for (int k0 = 0; k0 < K; k0 += 8) {
        float4 av = make_float4(0.f, 0.f, 0.f, 0.f);
        float4 bv = make_float4(0.f, 0.f, 0.f, 0.f);
        if (bm + lrow < M) av = *(const float4*)&A[(size_t)(bm + lrow) * K + k0 + lk];
        if (bn + lrow < N) bv = *(const float4*)&Bm[(size_t)(bn + lrow) * K + k0 + lk];
        sA[lk + 0][lrow] = av.x; sA[lk + 1][lrow] = av.y;
        sA[lk + 2][lrow] = av.z; sA[lk + 3][lrow] = av.w;
        sB[lk + 0][lrow] = bv.x; sB[lk + 1][lrow] = bv.y;
        sB[lk + 2][lrow] = bv.z; sB[lk + 3][lrow] = bv.w;
        __syncthreads();
#pragma unroll
        for (int k = 0; k < 8; k++) {
            float a[8], bb[8];
            *(float4*)&a[0] = *(const float4*)&sA[k][ty * 8];
            *(float4*)&a[4] = *(const float4*)&sA[k][ty * 8 + 4];
            *(float4*)&bb[0] = *(const float4*)&sB[k][tx * 8];
            *(float4*)&bb[4] = *(const float4*)&sB[k][tx * 8 + 4];
#pragma unroll
            for (int i = 0; i < 8; i++)
#pragma unroll
                for (int j = 0; j < 8; j++) acc[i][j] += a[i] * bb[j];
        }
        __syncthreads();
    }
    for (int i = 0; i < 8; i++) {
        int m = bm + ty * 8 + i;
        if (m >= M) break;
        for (int j = 0; j < 8; j++) {
            int n = bn + tx * 8 + j;
            if (n < N) C[(size_t)m * N + n] = acc[i][j] + bias[n];
        }
    }
}

// ---------------- encoder GRU: one block per batch element ----------------
// 384 threads; w_hh resident in smem, PADDED stride 132 (conflict-free float4).
__global__ void encoder_kernel(const float* __restrict__ w_hh,
                               const float* __restrict__ b_hh) {
    extern __shared__ float sm[];
    float* s_w = sm;              // 384*132 = 50688
    float* s_h = sm + 50688;      // 128
    float* s_gh = sm + 50816;     // 384
    int b = blockIdx.x, tid = threadIdx.x;
    for (int i = tid; i < 49152; i += 384) {
        int r = i >> 7, c = i & 127;
        s_w[r * 132 + c] = w_hh[i];
    }
    if (tid < 128) s_h[tid] = 0.f;
    __syncthreads();
    float bn = b_hh[tid];
    const float4* wr = (const float4*)&s_w[tid * 132];
    for (int t = 0; t < 105; t++) {
        float a0 = bn, a1 = 0.f;
#pragma unroll
        for (int k = 0; k < 16; k++) {
            float4 wv = wr[2 * k];
            float4 hv = ((const float4*)s_h)[2 * k];
            a0 += wv.x * hv.x + wv.y * hv.y + wv.z * hv.z + wv.w * hv.w;
            float4 wv2 = wr[2 * k + 1];
            float4 hv2 = ((const float4*)s_h)[2 * k + 1];
            a1 += wv2.x * hv2.x + wv2.y * hv2.y + wv2.z * hv2.z + wv2.w * hv2.w;
        }
        s_gh[tid] = a0 + a1;
        __syncthreads();
        if (tid < 128) {
            const float* xrow = &g_xp[((size_t)b * 105 + t) * 384];
            float r = 1.f / (1.f + __expf(-(xrow[tid] + s_gh[tid])));
            float z = 1.f / (1.f + __expf(-(xrow[128 + tid] + s_gh[128 + tid])));
            float nn = tanhf(xrow[256 + tid] + r * s_gh[256 + tid]);
            float hnew = (1.f - z) * nn + z * s_h[tid];
            s_h[tid] = hnew;
            g_eh[((size_t)b * 105 + t) * 128 + tid] = hnew;
        }
        __syncthreads();
    }
}

// ---------------- decoder: GRU step + attention, one block per batch ----------------
__device__ __forceinline__ float warpred_max(float v) {
#pragma unroll
    for (int o = 16; o; o >>= 1) v = fmaxf(v, __shfl_xor_sync(0xffffffffu, v, o));
    return v;
}
__device__ __forceinline__ float warpred_sum(float v) {
#pragma unroll
    for (int o = 16; o; o >>= 1) v += __shfl_xor_sync(0xffffffffu, v, o);
    return v;
}

__global__ void decoder_kernel(const float* __restrict__ b_hh) {
    extern __shared__ float sm[];
    float* s_eh = sm;              // 105*132 = 13860 (padded stride)
    float* s_h = sm + 13860;       // 128 (carry = ctx)
    float* s_gh = sm + 13988;      // 384
    float* s_hx2 = sm + 14372;     // 128
    float* s_att = sm + 14500;     // 128
    float* s_red = sm + 14628;     // 32
    int b = blockIdx.x, tid = threadIdx.x;

    for (int i = tid; i < 13440; i += 384) {
        int t = i >> 7, k = i & 127;
        s_eh[t * 132 + k] = g_eh[(size_t)b * 105 * 128 + i];
    }
    if (tid < 128) s_h[tid] = 0.f;
    __syncthreads();

    float bn = b_hh[tid];
    for (int l = 0; l < 63; l++) {
        // gh = hx @ w_hh^T + b (k-major w from global: coalesced, L2-resident)
        float a0 = bn, a1 = 0.f;
#pragma unroll 8
        for (int k = 0; k < 64; k++) {
            a0 += g_wT[k * 384 + tid] * s_h[k];
            a1 += g_wT[(k + 64) * 384 + tid] * s_h[k + 64];
        }
        s_gh[tid] = a0 + a1;
        __syncthreads();

        if (tid < 128) {
            const float* irow = &g_ip[((size_t)b * 63 + l) * 384];
            float r = 1.f / (1.f + __expf(-(irow[tid] + s_gh[tid])));
            float z = 1.f / (1.f + __expf(-(irow[128 + tid] + s_gh[128 + tid])));
            float nn = tanhf(irow[256 + tid] + r * s_gh[256 + tid]);
            s_hx2[tid] = (1.f - z) * nn + z * s_h[tid];
        }
        __syncthreads();

        // attention scores over 105 encoder states
        float sc = -1e30f;
        if (tid < 105) {
            const float4* er = (const float4*)&s_eh[tid * 132];
            const float4* hx = (const float4*)s_hx2;
            float d = 0.f;
#pragma unroll 8
            for (int k = 0; k < 32; k++) {
                float4 e4 = er[k], h4 = hx[k];
                d += e4.x * h4.x + e4.y * h4.y + e4.z * h4.z + e4.w * h4.w;
            }
            sc = d;
        }
        float m = warpred_max(sc);
        if ((tid & 31) == 0) s_red[tid >> 5] = m;
        __syncthreads();
        if (tid < 32) {
            float wv = (tid < 12) ? s_red[tid] : -1e30f;
            wv = warpred_max(wv);
            if (tid == 0) s_red[12] = wv;
        }
        __syncthreads();
        float mx = s_red[12];
        float e = (tid < 105) ? __expf(sc - mx) : 0.f;
        float sv = warpred_sum(e);
        if ((tid & 31) == 0) s_red[16 + (tid >> 5)] = sv;
        if (tid < 128) s_att[tid] = e;
        __syncthreads();
        if (tid < 32) {
            float wv = (tid < 12) ? s_red[16 + tid] : 0.f;
            wv = warpred_sum(wv);
            if (tid == 0) s_red[13] = wv;
        }
        __syncthreads();
        float inv = 1.f / s_red[13];

        if (tid < 128) {
            float c = 0.f;
            for (int t = 0; t < 105; t++) c += s_att[t] * s_eh[t * 132 + tid];
            c *= inv;
            s_h[tid] = c;
            g_ctxs[((size_t)b * 63 + l) * 128 + tid] = c;
        }
        __syncthreads();
    }
}

// ---------------- small helpers ----------------
__global__ void emb_gather(const int* __restrict__ y, const float* __restrict__ emb) {
    int i = blockIdx.x * 256 + threadIdx.x;
    if (i >= NB * 63 * 32) return;
    int m = i >> 5, e = i & 31;
    int bb = m / 63, l = m % 63;
    int idx = y[bb * 64 + l];
    g_embA[i] = emb[idx * 32 + e];
}

__global__ void transpose_whh(const float* __restrict__ w) {
    int i = blockIdx.x * 256 + threadIdx.x;
    if (i < 49152) {
        int n = i >> 7, k = i & 127;
        g_wT[k * 384 + n] = w[i];
    }
}

// ---------------- launch ----------------
extern "C" void kernel_launch(void* const* d_in, const int* in_sizes, int n_in,
                              void* d_out, int out_size) {
    const float* x    = (const float*)d_in[0];
    const int*   y    = (const int*)d_in[1];
    const float* mean = (const float*)d_in[2];
    const float* stdv = (const float*)d_in[3];
    const float* c1w  = (const float*)d_in[4];
    const float* c1b  = (const float*)d_in[5];
    const float* c2w  = (const float*)d_in[6];
    const float* c2b  = (const float*)d_in[7];
    const float* gwih = (const float*)d_in[8];
    const float* gwhh = (const float*)d_in[9];
    const float* gbih = (const float*)d_in[10];
    const float* gbhh = (const float*)d_in[11];
    const float* emb  = (const float*)d_in[12];
    const float* dwih = (const float*)d_in[13];
    const float* dwhh = (const float*)d_in[14];
    const float* dbih = (const float*)d_in[15];
    const float* dbhh = (const float*)d_in[16];
    const float* fcw  = (const float*)d_in[17];
    const float* fcb  = (const float*)d_in[18];
    float* out = (float*)d_out;

    cudaFuncSetAttribute(encoder_kernel, cudaFuncAttributeMaxDynamicSharedMemorySize, 204800);
    cudaFuncSetAttribute(decoder_kernel, cudaFuncAttributeMaxDynamicSharedMemorySize, 58640);
    cudaFuncSetAttribute(conv2_kernel, cudaFuncAttributeMaxDynamicSharedMemorySize, 57344);

    void *p_conv2, *p_xp, *p_embA, *p_ip, *p_ctxs;
    cudaGetSymbolAddress(&p_conv2, g_conv2);
    cudaGetSymbolAddress(&p_xp, g_xp);
    cudaGetSymbolAddress(&p_embA, g_embA);
    cudaGetSymbolAddress(&p_ip, g_ip);
    cudaGetSymbolAddress(&p_ctxs, g_ctxs);

    reorder_w2<<<(294912 + 255) / 256, 256>>>(c2w);
    transpose_whh<<<192, 256>>>(dwhh);
    conv1_kernel<<<dim3(C1H, NB), 256>>>(x, mean, stdv, c1w, c1b);
    conv2_kernel<<<dim3(53, NB), 384, 57344>>>(c2b);
    // xp = conv_out @ gru_w_ih^T + gru_b_ih : (6720,1152)x(384,1152)
    gemm_nt<<<dim3(3, 53), 256>>>((const float*)p_conv2, gwih, gbih, (float*)p_xp,
                                  NB * C2H, 384, 1152);
    encoder_kernel<<<NB, 384, 204800>>>(gwhh, gbhh);

    emb_gather<<<(NB * 63 * 32 + 255) / 256, 256>>>(y, emb);
    // ip = emb_in @ dec_w_ih^T + dec_b_ih : (4032,32)x(384,32)
    gemm_nt<<<dim3(3, 32), 256>>>((const float*)p_embA, dwih, dbih, (float*)p_ip,
                                  NB * 63, 384, 32);
    decoder_kernel<<<NB, 384, 58640>>>(dbhh);
    // out = ctxs @ fc_w^T + fc_b : (4032,128)x(32,128)
    gemm_nt<<<dim3(1, 32), 256>>>((const float*)p_ctxs, fcw, fcb, out,
                                  NB * 63, 32, 128);
}